// round 7
// baseline (speedup 1.0000x reference)
#include <cuda_runtime.h>
#include <cstdint>

#define T_STEPS 512
#define BATCH   32
#define HID     512
#define G4      2048
#define NBLK    128
#define STRIDE  516
#define WSTR    516
#define PSTR    20
#define ROUNDS  (T_STEPS + 2)
#define SECT    ((size_t)2 * T_STEPS * BATCH * HID)

// ---------------- device scratch ----------------
__device__ __align__(16) float g_pre[(size_t)T_STEPS * BATCH * G4];  // layer-0 pre-projection
__device__ __align__(16) float g_h0[2][BATCH * HID];                 // h ring, layer 0
__device__ __align__(16) float g_h1[2][BATCH * HID];                 // h ring, layer 1
__device__ unsigned g_bar;

__global__ void reset_bar() { g_bar = 0u; }

// ================= pre-projection GEMM (layer 0 only): tf32 tensor cores =================
#define KSTR 136

__device__ __forceinline__ unsigned f2tf32(float f) {
    unsigned u;
    asm("cvt.rna.tf32.f32 %0, %1;" : "=r"(u) : "f"(f));
    return u;
}

__device__ __forceinline__ void mma_tf32(float c[4], const unsigned a[4],
                                         unsigned b0, unsigned b1) {
    asm volatile(
        "mma.sync.aligned.m16n8k8.row.col.f32.tf32.tf32.f32 "
        "{%0,%1,%2,%3}, {%4,%5,%6,%7}, {%8,%9}, {%0,%1,%2,%3};"
        : "+f"(c[0]), "+f"(c[1]), "+f"(c[2]), "+f"(c[3])
        : "r"(a[0]), "r"(a[1]), "r"(a[2]), "r"(a[3]), "r"(b0), "r"(b1));
}

__global__ void __launch_bounds__(256) pre_gemm_tc(
    const float* __restrict__ A, const float* __restrict__ W,
    const float* __restrict__ bih, const float* __restrict__ bhh)
{
    __shared__ unsigned As[2][16 * KSTR];
    __shared__ unsigned Ws[2][16 * KSTR];

    const int tid  = threadIdx.x;
    const int brow = blockIdx.x * 128;
    const int bcol = blockIdx.y * 128;
    const int lane = tid & 31, wid = tid >> 5;
    const int grp  = lane >> 2, tg = lane & 3;
    const int m0w  = (wid & 3) * 32;
    const int n0w  = (wid >> 2) * 64;

    const int sr0 = tid >> 2,         sk0 = (tid & 3) << 2;
    const int sr1 = (tid + 256) >> 2, sk1 = sk0;

    float c[2][8][4];
#pragma unroll
    for (int mt = 0; mt < 2; mt++)
#pragma unroll
        for (int nt = 0; nt < 8; nt++)
#pragma unroll
            for (int i = 0; i < 4; i++) c[mt][nt][i] = 0.f;

    const float* Ap = A + (size_t)brow * HID;
    const float* Wp = W + (size_t)bcol * HID;

    {
        float4 a0 = *(const float4*)(Ap + (size_t)sr0 * HID + sk0);
        float4 a1 = *(const float4*)(Ap + (size_t)sr1 * HID + sk1);
        float4 w0 = *(const float4*)(Wp + (size_t)sr0 * HID + sk0);
        float4 w1 = *(const float4*)(Wp + (size_t)sr1 * HID + sk1);
        As[0][(sk0 + 0) * KSTR + sr0] = f2tf32(a0.x);
        As[0][(sk0 + 1) * KSTR + sr0] = f2tf32(a0.y);
        As[0][(sk0 + 2) * KSTR + sr0] = f2tf32(a0.z);
        As[0][(sk0 + 3) * KSTR + sr0] = f2tf32(a0.w);
        As[0][(sk1 + 0) * KSTR + sr1] = f2tf32(a1.x);
        As[0][(sk1 + 1) * KSTR + sr1] = f2tf32(a1.y);
        As[0][(sk1 + 2) * KSTR + sr1] = f2tf32(a1.z);
        As[0][(sk1 + 3) * KSTR + sr1] = f2tf32(a1.w);
        Ws[0][(sk0 + 0) * KSTR + sr0] = f2tf32(w0.x);
        Ws[0][(sk0 + 1) * KSTR + sr0] = f2tf32(w0.y);
        Ws[0][(sk0 + 2) * KSTR + sr0] = f2tf32(w0.z);
        Ws[0][(sk0 + 3) * KSTR + sr0] = f2tf32(w0.w);
        Ws[0][(sk1 + 0) * KSTR + sr1] = f2tf32(w1.x);
        Ws[0][(sk1 + 1) * KSTR + sr1] = f2tf32(w1.y);
        Ws[0][(sk1 + 2) * KSTR + sr1] = f2tf32(w1.z);
        Ws[0][(sk1 + 3) * KSTR + sr1] = f2tf32(w1.w);
    }

    int buf = 0;
    for (int kt = 0; kt < 32; kt++) {
        const bool nxt = (kt + 1) < 32;
        float4 na0, na1, nw0, nw1;
        if (nxt) {
            const int k0 = (kt + 1) * 16;
            na0 = *(const float4*)(Ap + (size_t)sr0 * HID + k0 + sk0);
            na1 = *(const float4*)(Ap + (size_t)sr1 * HID + k0 + sk1);
            nw0 = *(const float4*)(Wp + (size_t)sr0 * HID + k0 + sk0);
            nw1 = *(const float4*)(Wp + (size_t)sr1 * HID + k0 + sk1);
        }
        __syncthreads();

        const unsigned* Asb = As[buf];
        const unsigned* Wsb = Ws[buf];
#pragma unroll
        for (int k8 = 0; k8 < 16; k8 += 8) {
            unsigned af[2][4];
#pragma unroll
            for (int mt = 0; mt < 2; mt++) {
                const int m = m0w + mt * 16 + grp;
                af[mt][0] = Asb[(k8 + tg) * KSTR + m];
                af[mt][1] = Asb[(k8 + tg) * KSTR + m + 8];
                af[mt][2] = Asb[(k8 + tg + 4) * KSTR + m];
                af[mt][3] = Asb[(k8 + tg + 4) * KSTR + m + 8];
            }
#pragma unroll
            for (int nt = 0; nt < 8; nt++) {
                const int n = n0w + nt * 8 + grp;
                unsigned b0 = Wsb[(k8 + tg) * KSTR + n];
                unsigned b1 = Wsb[(k8 + tg + 4) * KSTR + n];
                mma_tf32(c[0][nt], af[0], b0, b1);
                mma_tf32(c[1][nt], af[1], b0, b1);
            }
        }

        if (nxt) {
            __syncthreads();
            const int nb = buf ^ 1;
            As[nb][(sk0 + 0) * KSTR + sr0] = f2tf32(na0.x);
            As[nb][(sk0 + 1) * KSTR + sr0] = f2tf32(na0.y);
            As[nb][(sk0 + 2) * KSTR + sr0] = f2tf32(na0.z);
            As[nb][(sk0 + 3) * KSTR + sr0] = f2tf32(na0.w);
            As[nb][(sk1 + 0) * KSTR + sr1] = f2tf32(na1.x);
            As[nb][(sk1 + 1) * KSTR + sr1] = f2tf32(na1.y);
            As[nb][(sk1 + 2) * KSTR + sr1] = f2tf32(na1.z);
            As[nb][(sk1 + 3) * KSTR + sr1] = f2tf32(na1.w);
            Ws[nb][(sk0 + 0) * KSTR + sr0] = f2tf32(nw0.x);
            Ws[nb][(sk0 + 1) * KSTR + sr0] = f2tf32(nw0.y);
            Ws[nb][(sk0 + 2) * KSTR + sr0] = f2tf32(nw0.z);
            Ws[nb][(sk0 + 3) * KSTR + sr0] = f2tf32(nw0.w);
            Ws[nb][(sk1 + 0) * KSTR + sr1] = f2tf32(nw1.x);
            Ws[nb][(sk1 + 1) * KSTR + sr1] = f2tf32(nw1.y);
            Ws[nb][(sk1 + 2) * KSTR + sr1] = f2tf32(nw1.z);
            Ws[nb][(sk1 + 3) * KSTR + sr1] = f2tf32(nw1.w);
        }
        buf ^= 1;
    }

#pragma unroll
    for (int nt = 0; nt < 8; nt++) {
        const int colg = bcol + n0w + nt * 8 + 2 * tg;
        const float bb0 = bih[colg] + bhh[colg];
        const float bb1 = bih[colg + 1] + bhh[colg + 1];
#pragma unroll
        for (int mt = 0; mt < 2; mt++) {
            const int row = brow + m0w + mt * 16 + grp;
            float2 o0 = make_float2(c[mt][nt][0] + bb0, c[mt][nt][1] + bb1);
            float2 o1 = make_float2(c[mt][nt][2] + bb0, c[mt][nt][3] + bb1);
            *(float2*)&g_pre[(size_t)row * G4 + colg]       = o0;
            *(float2*)&g_pre[(size_t)(row + 8) * G4 + colg] = o1;
        }
    }
}

// ================= fused 2-layer wavefront recurrence =================
#define FMA2(d, a, b) \
    asm("fma.rn.f32x2 %0, %1, %2, %0;" : "+l"(d) : "l"(a), "l"(b))

// one 16-col x 512-k matvec pass: per-thread 32-k chunk over 16 batches
__device__ __forceinline__ void mv_pass(const float* __restrict__ hp,
                                        const ulonglong2 wq[8],
                                        float* __restrict__ pr)
{
    unsigned long long acc2[16];
#pragma unroll
    for (int b = 0; b < 16; b++) acc2[b] = 0ull;
#pragma unroll
    for (int q = 0; q < 8; q++) {
        const unsigned long long wlo = wq[q].x, whi = wq[q].y;
#pragma unroll
        for (int b = 0; b < 16; b++) {
            ulonglong2 h2 = *(const ulonglong2*)(hp + (size_t)b * STRIDE + q * 4);
            FMA2(acc2[b], h2.x, wlo);
            FMA2(acc2[b], h2.y, whi);
        }
    }
#pragma unroll
    for (int b4 = 0; b4 < 4; b4++) {
        float4 v;
        v.x = __uint_as_float((unsigned)acc2[b4 * 4 + 0]) + __uint_as_float((unsigned)(acc2[b4 * 4 + 0] >> 32));
        v.y = __uint_as_float((unsigned)acc2[b4 * 4 + 1]) + __uint_as_float((unsigned)(acc2[b4 * 4 + 1] >> 32));
        v.z = __uint_as_float((unsigned)acc2[b4 * 4 + 2]) + __uint_as_float((unsigned)(acc2[b4 * 4 + 2] >> 32));
        v.w = __uint_as_float((unsigned)acc2[b4 * 4 + 3]) + __uint_as_float((unsigned)(acc2[b4 * 4 + 3] >> 32));
        *(float4*)(pr + b4 * 4) = v;
    }
}

__global__ void __launch_bounds__(512, 1) lstm_fused(
    const float* __restrict__ whh0, const float* __restrict__ wih1,
    const float* __restrict__ whh1,
    const float* __restrict__ bih1, const float* __restrict__ bhh1,
    float* __restrict__ out)
{
    extern __shared__ float sm[];
    float* h0_s  = sm;                                   // [32][STRIDE]
    float* h1_s  = sm + 32 * STRIDE;                     // [32][STRIDE]
    float* part  = sm + 64 * STRIDE;                     // [512][PSTR]
    float* w2_s  = sm + 64 * STRIDE + 512 * PSTR;        // [16][WSTR]  (Whh1 slice)
    float* pre1s = sm + 64 * STRIDE + 512 * PSTR + 16 * WSTR;  // [2][32*16]

    const int tid  = threadIdx.x;
    const int col  = tid & 15;
    const int ksub = (tid >> 4) & 15;
    const int bh   = tid >> 8;
    const int jblk = blockIdx.x;
    const int gate = col >> 2, jj = col & 3;
    const int wrow = gate * HID + jblk * 4 + jj;

    // Whh0 chunk in registers (whole kernel)
    ulonglong2 wq0[8];
    {
        const float* wp = whh0 + (size_t)wrow * HID + ksub * 32;
#pragma unroll
        for (int q = 0; q < 8; q++) wq0[q] = *(const ulonglong2*)(wp + q * 4);
    }
    // Whh1 slice persistent in SMEM
    for (int i = tid; i < 16 * 128; i += 512) {
        int c = i >> 7, kq = (i & 127) << 2;
        int row = (c >> 2) * HID + jblk * 4 + (c & 3);
        *(float4*)&w2_s[c * WSTR + kq] = *(const float4*)&whh1[(size_t)row * HID + kq];
    }
    const float* w1p = wih1 + (size_t)wrow * HID + ksub * 32;  // streamed each round

    const float bias1 = bih1[wrow] + bhh1[wrow];

    // epilogue thread mapping (tid<128): one (b, j) cell per layer
    const int ajj = tid & 3;
    const int ab  = (tid >> 2) & 31;
    const int aj  = jblk * 4 + ajj;
    const int bhi = ab >> 4, bl = ab & 15;
    float c0 = 0.f, c1 = 0.f;

    float* prth = part + (size_t)(((ksub * 2 + bh) * 16 + col) * PSTR);
    const float* hp0 = h0_s + (size_t)(bh * 16) * STRIDE + ksub * 32;
    const float* hp1 = h1_s + (size_t)(bh * 16) * STRIDE + ksub * 32;

    for (int r = 0; r < ROUNDS; r++) {
        // ---- prefetch layer-0 pre-projection (DRAM stream) ----
        float pre0g[4] = {0.f, 0.f, 0.f, 0.f};
        if (tid < 128 && r < T_STEPS) {
            const float* pp = g_pre + ((size_t)r * BATCH + ab) * G4 + aj;
#pragma unroll
            for (int g = 0; g < 4; g++) pre0g[g] = __ldg(pp + g * HID);
        }

        // ---- stage h0[r-1], h1[r-3] ----
        if (r == 0) {
#pragma unroll
            for (int q = 0; q < 8; q++) {
                int lin = q * 512 + tid;
                int b = lin >> 7, kq = (lin & 127) << 2;
                *(float4*)&h0_s[b * STRIDE + kq] = make_float4(0.f, 0.f, 0.f, 0.f);
            }
        } else {
            const float* hb = g_h0[(r + 1) & 1];
#pragma unroll
            for (int q = 0; q < 8; q++) {
                int lin = q * 512 + tid;
                int b = lin >> 7, kq = (lin & 127) << 2;
                *(float4*)&h0_s[b * STRIDE + kq] = __ldcg((const float4*)(hb + b * HID + kq));
            }
        }
        if (r < 3) {
#pragma unroll
            for (int q = 0; q < 8; q++) {
                int lin = q * 512 + tid;
                int b = lin >> 7, kq = (lin & 127) << 2;
                *(float4*)&h1_s[b * STRIDE + kq] = make_float4(0.f, 0.f, 0.f, 0.f);
            }
        } else {
            const float* hb = g_h1[(r + 1) & 1];
#pragma unroll
            for (int q = 0; q < 8; q++) {
                int lin = q * 512 + tid;
                int b = lin >> 7, kq = (lin & 127) << 2;
                *(float4*)&h1_s[b * STRIDE + kq] = __ldcg((const float4*)(hb + b * HID + kq));
            }
        }
        __syncthreads();

        // ============ pass 0: layer-0 gates = Whh0 @ h0[r-1] ============
        mv_pass(hp0, wq0, prth);
        __syncthreads();
        if (tid < 128 && r < T_STEPS) {
            float gs[4];
#pragma unroll
            for (int g = 0; g < 4; g++) {
                int c = g * 4 + ajj;
                float s = pre0g[g];
#pragma unroll
                for (int ks = 0; ks < 16; ks++)
                    s += part[((ks * 2 + bhi) * 16 + c) * PSTR + bl];
                gs[g] = s;
            }
            float i_t = 1.f / (1.f + __expf(-gs[0]));
            float f_t = 1.f / (1.f + __expf(-gs[1]));
            float g_t = __fdividef(2.f, 1.f + __expf(-2.f * gs[2])) - 1.f;
            float o_t = 1.f / (1.f + __expf(-gs[3]));
            float c_new = f_t * c0 + i_t * g_t;
            float tc    = __fdividef(2.f, 1.f + __expf(-2.f * c_new)) - 1.f;
            float h_new = o_t * tc;
            c0 = c_new;
            size_t oidx = ((size_t)r * BATCH + ab) * HID + aj;
            out[oidx]            = h_new;
            out[SECT + oidx]     = c_new;
            out[2 * SECT + oidx] = i_t;
            out[3 * SECT + oidx] = f_t;
            out[4 * SECT + oidx] = g_t;
            out[5 * SECT + oidx] = o_t;
            g_h0[r & 1][ab * HID + aj] = h_new;
        }
        __syncthreads();

        // ============ pass 1: pre1[r-1] = bias1 + Wih1 @ h0[r-1] ============
        {
            ulonglong2 wq[8];
#pragma unroll
            for (int q = 0; q < 8; q++)
                wq[q] = *(const ulonglong2*)__builtin_assume_aligned(w1p + q * 4, 16);
            mv_pass(hp0, wq, prth);
        }
        __syncthreads();
        if (r >= 1 && r < T_STEPS + 1) {
            const int bfull = tid >> 4;
            float s = bias1;
#pragma unroll
            for (int ks = 0; ks < 16; ks++)
                s += part[((ks * 2 + (bfull >> 4)) * 16 + col) * PSTR + (bfull & 15)];
            pre1s[((r - 1) & 1) * 512 + bfull * 16 + col] = s;
        }
        __syncthreads();

        // ============ pass 2: layer-1 gates = pre1[r-2] + Whh1 @ h1[r-3] ============
        {
            ulonglong2 wq[8];
            const float* w2p = w2_s + col * WSTR + ksub * 32;
#pragma unroll
            for (int q = 0; q < 8; q++) wq[q] = *(const ulonglong2*)(w2p + q * 4);
            mv_pass(hp1, wq, prth);
        }
        __syncthreads();
        if (tid < 128 && r >= 2) {
            const int t = r - 2;
            float gs[4];
#pragma unroll
            for (int g = 0; g < 4; g++) {
                int c = g * 4 + ajj;
                float s = pre1s[(r & 1) * 512 + ab * 16 + c];
#pragma unroll
                for (int ks = 0; ks < 16; ks++)
                    s += part[((ks * 2 + bhi) * 16 + c) * PSTR + bl];
                gs[g] = s;
            }
            float i_t = 1.f / (1.f + __expf(-gs[0]));
            float f_t = 1.f / (1.f + __expf(-gs[1]));
            float g_t = __fdividef(2.f, 1.f + __expf(-2.f * gs[2])) - 1.f;
            float o_t = 1.f / (1.f + __expf(-gs[3]));
            float c_new = f_t * c1 + i_t * g_t;
            float tc    = __fdividef(2.f, 1.f + __expf(-2.f * c_new)) - 1.f;
            float h_new = o_t * tc;
            c1 = c_new;
            size_t oidx = ((size_t)(T_STEPS + t) * BATCH + ab) * HID + aj;
            out[oidx]            = h_new;
            out[SECT + oidx]     = c_new;
            out[2 * SECT + oidx] = i_t;
            out[3 * SECT + oidx] = f_t;
            out[4 * SECT + oidx] = g_t;
            out[5 * SECT + oidx] = o_t;
            g_h1[r & 1][ab * HID + aj] = h_new;
        }
        __syncthreads();

        // ---- grid barrier ----
        if (tid == 0) {
            asm volatile("red.release.gpu.global.add.u32 [%0], 1;" :: "l"(&g_bar) : "memory");
            const unsigned target = (unsigned)(r + 1) * NBLK;
            unsigned v;
            do {
                asm volatile("ld.acquire.gpu.global.u32 %0, [%1];" : "=r"(v) : "l"(&g_bar) : "memory");
            } while (v < target);
        }
        __syncthreads();
    }
}

// ---------------- launch ----------------
extern "C" void kernel_launch(void* const* d_in, const int* in_sizes, int n_in,
                              void* d_out, int out_size)
{
    (void)in_sizes; (void)n_in; (void)out_size;
    const float* x    = (const float*)d_in[0];
    const float* w_ih = (const float*)d_in[1];
    const float* w_hh = (const float*)d_in[2];
    const float* b_ih = (const float*)d_in[3];
    const float* b_hh = (const float*)d_in[4];
    float* out = (float*)d_out;

    const int smem = (64 * STRIDE + 512 * PSTR + 16 * WSTR + 2 * 512) * 4;  // 210176 B
    cudaFuncSetAttribute(lstm_fused, cudaFuncAttributeMaxDynamicSharedMemorySize, smem);

    dim3 gg(T_STEPS * BATCH / 128, G4 / 128);  // (128, 16)
    pre_gemm_tc<<<gg, 256>>>(x, w_ih, b_ih, b_hh);   // layer 0 only
    reset_bar<<<1, 1>>>();
    lstm_fused<<<NBLK, 512, smem>>>(w_hh,
                                    w_ih + (size_t)G4 * HID,
                                    w_hh + (size_t)G4 * HID,
                                    b_ih + G4, b_hh + G4, out);
}

// round 9
// speedup vs baseline: 1.3880x; 1.3880x over previous
#include <cuda_runtime.h>
#include <cstdint>

#define T_STEPS 512
#define BATCH   32
#define HID     512
#define G4      2048
#define NBLK    128
#define STRIDE  516
#define WSTR    516
#define PSTR    20
#define ROUNDS  (T_STEPS + 2)
#define SECT    ((size_t)2 * T_STEPS * BATCH * HID)

// ---------------- device scratch ----------------
__device__ __align__(16) float g_pre[(size_t)T_STEPS * BATCH * G4];  // layer-0 pre-projection
__device__ __align__(16) float g_h0[2][BATCH * HID];                 // h ring, layer 0
__device__ __align__(16) float g_h1[2][BATCH * HID];                 // h ring, layer 1
__device__ unsigned g_bar;

__global__ void reset_bar() { g_bar = 0u; }

// ================= pre-projection GEMM (layer 0 only): tf32 tensor cores =================
#define KSTR 136

__device__ __forceinline__ unsigned f2tf32(float f) {
    unsigned u;
    asm("cvt.rna.tf32.f32 %0, %1;" : "=r"(u) : "f"(f));
    return u;
}

__device__ __forceinline__ void mma_tf32(float c[4], const unsigned a[4],
                                         unsigned b0, unsigned b1) {
    asm volatile(
        "mma.sync.aligned.m16n8k8.row.col.f32.tf32.tf32.f32 "
        "{%0,%1,%2,%3}, {%4,%5,%6,%7}, {%8,%9}, {%0,%1,%2,%3};"
        : "+f"(c[0]), "+f"(c[1]), "+f"(c[2]), "+f"(c[3])
        : "r"(a[0]), "r"(a[1]), "r"(a[2]), "r"(a[3]), "r"(b0), "r"(b1));
}

__global__ void __launch_bounds__(256) pre_gemm_tc(
    const float* __restrict__ A, const float* __restrict__ W,
    const float* __restrict__ bih, const float* __restrict__ bhh)
{
    __shared__ unsigned As[2][16 * KSTR];
    __shared__ unsigned Ws[2][16 * KSTR];

    const int tid  = threadIdx.x;
    const int brow = blockIdx.x * 128;
    const int bcol = blockIdx.y * 128;
    const int lane = tid & 31, wid = tid >> 5;
    const int grp  = lane >> 2, tg = lane & 3;
    const int m0w  = (wid & 3) * 32;
    const int n0w  = (wid >> 2) * 64;

    const int sr0 = tid >> 2,         sk0 = (tid & 3) << 2;
    const int sr1 = (tid + 256) >> 2, sk1 = sk0;

    float c[2][8][4];
#pragma unroll
    for (int mt = 0; mt < 2; mt++)
#pragma unroll
        for (int nt = 0; nt < 8; nt++)
#pragma unroll
            for (int i = 0; i < 4; i++) c[mt][nt][i] = 0.f;

    const float* Ap = A + (size_t)brow * HID;
    const float* Wp = W + (size_t)bcol * HID;

    {
        float4 a0 = *(const float4*)(Ap + (size_t)sr0 * HID + sk0);
        float4 a1 = *(const float4*)(Ap + (size_t)sr1 * HID + sk1);
        float4 w0 = *(const float4*)(Wp + (size_t)sr0 * HID + sk0);
        float4 w1 = *(const float4*)(Wp + (size_t)sr1 * HID + sk1);
        As[0][(sk0 + 0) * KSTR + sr0] = f2tf32(a0.x);
        As[0][(sk0 + 1) * KSTR + sr0] = f2tf32(a0.y);
        As[0][(sk0 + 2) * KSTR + sr0] = f2tf32(a0.z);
        As[0][(sk0 + 3) * KSTR + sr0] = f2tf32(a0.w);
        As[0][(sk1 + 0) * KSTR + sr1] = f2tf32(a1.x);
        As[0][(sk1 + 1) * KSTR + sr1] = f2tf32(a1.y);
        As[0][(sk1 + 2) * KSTR + sr1] = f2tf32(a1.z);
        As[0][(sk1 + 3) * KSTR + sr1] = f2tf32(a1.w);
        Ws[0][(sk0 + 0) * KSTR + sr0] = f2tf32(w0.x);
        Ws[0][(sk0 + 1) * KSTR + sr0] = f2tf32(w0.y);
        Ws[0][(sk0 + 2) * KSTR + sr0] = f2tf32(w0.z);
        Ws[0][(sk0 + 3) * KSTR + sr0] = f2tf32(w0.w);
        Ws[0][(sk1 + 0) * KSTR + sr1] = f2tf32(w1.x);
        Ws[0][(sk1 + 1) * KSTR + sr1] = f2tf32(w1.y);
        Ws[0][(sk1 + 2) * KSTR + sr1] = f2tf32(w1.z);
        Ws[0][(sk1 + 3) * KSTR + sr1] = f2tf32(w1.w);
    }

    int buf = 0;
    for (int kt = 0; kt < 32; kt++) {
        const bool nxt = (kt + 1) < 32;
        float4 na0, na1, nw0, nw1;
        if (nxt) {
            const int k0 = (kt + 1) * 16;
            na0 = *(const float4*)(Ap + (size_t)sr0 * HID + k0 + sk0);
            na1 = *(const float4*)(Ap + (size_t)sr1 * HID + k0 + sk1);
            nw0 = *(const float4*)(Wp + (size_t)sr0 * HID + k0 + sk0);
            nw1 = *(const float4*)(Wp + (size_t)sr1 * HID + k0 + sk1);
        }
        __syncthreads();

        const unsigned* Asb = As[buf];
        const unsigned* Wsb = Ws[buf];
#pragma unroll
        for (int k8 = 0; k8 < 16; k8 += 8) {
            unsigned af[2][4];
#pragma unroll
            for (int mt = 0; mt < 2; mt++) {
                const int m = m0w + mt * 16 + grp;
                af[mt][0] = Asb[(k8 + tg) * KSTR + m];
                af[mt][1] = Asb[(k8 + tg) * KSTR + m + 8];
                af[mt][2] = Asb[(k8 + tg + 4) * KSTR + m];
                af[mt][3] = Asb[(k8 + tg + 4) * KSTR + m + 8];
            }
#pragma unroll
            for (int nt = 0; nt < 8; nt++) {
                const int n = n0w + nt * 8 + grp;
                unsigned b0 = Wsb[(k8 + tg) * KSTR + n];
                unsigned b1 = Wsb[(k8 + tg + 4) * KSTR + n];
                mma_tf32(c[0][nt], af[0], b0, b1);
                mma_tf32(c[1][nt], af[1], b0, b1);
            }
        }

        if (nxt) {
            __syncthreads();
            const int nb = buf ^ 1;
            As[nb][(sk0 + 0) * KSTR + sr0] = f2tf32(na0.x);
            As[nb][(sk0 + 1) * KSTR + sr0] = f2tf32(na0.y);
            As[nb][(sk0 + 2) * KSTR + sr0] = f2tf32(na0.z);
            As[nb][(sk0 + 3) * KSTR + sr0] = f2tf32(na0.w);
            As[nb][(sk1 + 0) * KSTR + sr1] = f2tf32(na1.x);
            As[nb][(sk1 + 1) * KSTR + sr1] = f2tf32(na1.y);
            As[nb][(sk1 + 2) * KSTR + sr1] = f2tf32(na1.z);
            As[nb][(sk1 + 3) * KSTR + sr1] = f2tf32(na1.w);
            Ws[nb][(sk0 + 0) * KSTR + sr0] = f2tf32(nw0.x);
            Ws[nb][(sk0 + 1) * KSTR + sr0] = f2tf32(nw0.y);
            Ws[nb][(sk0 + 2) * KSTR + sr0] = f2tf32(nw0.z);
            Ws[nb][(sk0 + 3) * KSTR + sr0] = f2tf32(nw0.w);
            Ws[nb][(sk1 + 0) * KSTR + sr1] = f2tf32(nw1.x);
            Ws[nb][(sk1 + 1) * KSTR + sr1] = f2tf32(nw1.y);
            Ws[nb][(sk1 + 2) * KSTR + sr1] = f2tf32(nw1.z);
            Ws[nb][(sk1 + 3) * KSTR + sr1] = f2tf32(nw1.w);
        }
        buf ^= 1;
    }

#pragma unroll
    for (int nt = 0; nt < 8; nt++) {
        const int colg = bcol + n0w + nt * 8 + 2 * tg;
        const float bb0 = bih[colg] + bhh[colg];
        const float bb1 = bih[colg + 1] + bhh[colg + 1];
#pragma unroll
        for (int mt = 0; mt < 2; mt++) {
            const int row = brow + m0w + mt * 16 + grp;
            float2 o0 = make_float2(c[mt][nt][0] + bb0, c[mt][nt][1] + bb1);
            float2 o1 = make_float2(c[mt][nt][2] + bb0, c[mt][nt][3] + bb1);
            *(float2*)&g_pre[(size_t)row * G4 + colg]       = o0;
            *(float2*)&g_pre[(size_t)(row + 8) * G4 + colg] = o1;
        }
    }
}

// ================= fused 2-layer wavefront recurrence (spill-free) =================
#define FMA2(d, a, b) \
    asm("fma.rn.f32x2 %0, %1, %2, %0;" : "+l"(d) : "l"(a), "l"(b))

// one 16-col x 512-k matvec pass; w loaded by caller into wq (only live here)
__device__ __forceinline__ void mv_pass(const float* __restrict__ hp,
                                        const ulonglong2 wq[8],
                                        float* __restrict__ pr)
{
    unsigned long long acc2[16];
#pragma unroll
    for (int b = 0; b < 16; b++) acc2[b] = 0ull;
#pragma unroll
    for (int q = 0; q < 8; q++) {
        const unsigned long long wlo = wq[q].x, whi = wq[q].y;
#pragma unroll
        for (int b = 0; b < 16; b++) {
            ulonglong2 h2 = *(const ulonglong2*)(hp + (size_t)b * STRIDE + q * 4);
            FMA2(acc2[b], h2.x, wlo);
            FMA2(acc2[b], h2.y, whi);
        }
    }
#pragma unroll
    for (int b4 = 0; b4 < 4; b4++) {
        float4 v;
        v.x = __uint_as_float((unsigned)acc2[b4 * 4 + 0]) + __uint_as_float((unsigned)(acc2[b4 * 4 + 0] >> 32));
        v.y = __uint_as_float((unsigned)acc2[b4 * 4 + 1]) + __uint_as_float((unsigned)(acc2[b4 * 4 + 1] >> 32));
        v.z = __uint_as_float((unsigned)acc2[b4 * 4 + 2]) + __uint_as_float((unsigned)(acc2[b4 * 4 + 2] >> 32));
        v.w = __uint_as_float((unsigned)acc2[b4 * 4 + 3]) + __uint_as_float((unsigned)(acc2[b4 * 4 + 3] >> 32));
        *(float4*)(pr + b4 * 4) = v;
    }
}

__global__ void __launch_bounds__(512, 1) lstm_fused(
    const float* __restrict__ whh0, const float* __restrict__ wih1,
    const float* __restrict__ whh1,
    const float* __restrict__ bih1, const float* __restrict__ bhh1,
    float* __restrict__ out)
{
    extern __shared__ float sm[];
    float* h0_s  = sm;                                   // [32][STRIDE]
    float* h1_s  = sm + 32 * STRIDE;                     // [32][STRIDE]
    float* part  = sm + 64 * STRIDE;                     // [512][PSTR]
    float* w2_s  = sm + 64 * STRIDE + 512 * PSTR;        // [16][WSTR]  (Whh1 slice)
    float* pre1s = sm + 64 * STRIDE + 512 * PSTR + 16 * WSTR;  // [2][32*16]

    const int tid  = threadIdx.x;
    const int col  = tid & 15;
    const int ksub = (tid >> 4) & 15;
    const int bh   = tid >> 8;
    const int jblk = blockIdx.x;
    const int gate = col >> 2, jj = col & 3;
    const int wrow = gate * HID + jblk * 4 + jj;

    // Whh0 and Wih1 both streamed from global each round (L2-resident, 4 MB each).
    const float* w0p = whh0 + (size_t)wrow * HID + ksub * 32;
    const float* w1p = wih1 + (size_t)wrow * HID + ksub * 32;

    // Whh1 slice persistent in SMEM
    for (int i = tid; i < 16 * 128; i += 512) {
        int c = i >> 7, kq = (i & 127) << 2;
        int row = (c >> 2) * HID + jblk * 4 + (c & 3);
        *(float4*)&w2_s[c * WSTR + kq] = *(const float4*)&whh1[(size_t)row * HID + kq];
    }

    const float bias1 = bih1[wrow] + bhh1[wrow];

    const int ajj = tid & 3;
    const int ab  = (tid >> 2) & 31;
    const int aj  = jblk * 4 + ajj;
    const int bhi = ab >> 4, bl = ab & 15;
    float c0 = 0.f, c1 = 0.f;

    float* prth = part + (size_t)(((ksub * 2 + bh) * 16 + col) * PSTR);
    const float* hp0 = h0_s + (size_t)(bh * 16) * STRIDE + ksub * 32;
    const float* hp1 = h1_s + (size_t)(bh * 16) * STRIDE + ksub * 32;

    for (int r = 0; r < ROUNDS; r++) {
        // ---- prefetch layer-0 pre-projection ----
        float pre0g[4] = {0.f, 0.f, 0.f, 0.f};
        if (tid < 128 && r < T_STEPS) {
            const float* pp = g_pre + ((size_t)r * BATCH + ab) * G4 + aj;
#pragma unroll
            for (int g = 0; g < 4; g++) pre0g[g] = __ldg(pp + g * HID);
        }

        // ---- stage h0[r-1], h1[r-3] ----
        if (r == 0) {
#pragma unroll
            for (int q = 0; q < 8; q++) {
                int lin = q * 512 + tid;
                int b = lin >> 7, kq = (lin & 127) << 2;
                *(float4*)&h0_s[b * STRIDE + kq] = make_float4(0.f, 0.f, 0.f, 0.f);
            }
        } else {
            const float* hb = g_h0[(r + 1) & 1];
#pragma unroll
            for (int q = 0; q < 8; q++) {
                int lin = q * 512 + tid;
                int b = lin >> 7, kq = (lin & 127) << 2;
                *(float4*)&h0_s[b * STRIDE + kq] = __ldcg((const float4*)(hb + b * HID + kq));
            }
        }
        if (r < 3) {
#pragma unroll
            for (int q = 0; q < 8; q++) {
                int lin = q * 512 + tid;
                int b = lin >> 7, kq = (lin & 127) << 2;
                *(float4*)&h1_s[b * STRIDE + kq] = make_float4(0.f, 0.f, 0.f, 0.f);
            }
        } else {
            const float* hb = g_h1[(r + 1) & 1];
#pragma unroll
            for (int q = 0; q < 8; q++) {
                int lin = q * 512 + tid;
                int b = lin >> 7, kq = (lin & 127) << 2;
                *(float4*)&h1_s[b * STRIDE + kq] = __ldcg((const float4*)(hb + b * HID + kq));
            }
        }
        __syncthreads();

        // ============ pass 0: layer-0 gates = Whh0 @ h0[r-1] ============
        {
            ulonglong2 wq[8];
#pragma unroll
            for (int q = 0; q < 8; q++)
                wq[q] = *(const ulonglong2*)__builtin_assume_aligned(w0p + q * 4, 16);
            mv_pass(hp0, wq, prth);
        }
        __syncthreads();
        if (tid < 128 && r < T_STEPS) {
            float gs[4];
#pragma unroll
            for (int g = 0; g < 4; g++) {
                int c = g * 4 + ajj;
                float s = pre0g[g];
#pragma unroll
                for (int ks = 0; ks < 16; ks++)
                    s += part[((ks * 2 + bhi) * 16 + c) * PSTR + bl];
                gs[g] = s;
            }
            float i_t = 1.f / (1.f + __expf(-gs[0]));
            float f_t = 1.f / (1.f + __expf(-gs[1]));
            float g_t = __fdividef(2.f, 1.f + __expf(-2.f * gs[2])) - 1.f;
            float o_t = 1.f / (1.f + __expf(-gs[3]));
            float c_new = f_t * c0 + i_t * g_t;
            float tc    = __fdividef(2.f, 1.f + __expf(-2.f * c_new)) - 1.f;
            float h_new = o_t * tc;
            c0 = c_new;
            size_t oidx = ((size_t)r * BATCH + ab) * HID + aj;
            out[oidx]            = h_new;
            out[SECT + oidx]     = c_new;
            out[2 * SECT + oidx] = i_t;
            out[3 * SECT + oidx] = f_t;
            out[4 * SECT + oidx] = g_t;
            out[5 * SECT + oidx] = o_t;
            g_h0[r & 1][ab * HID + aj] = h_new;
        }
        __syncthreads();

        // ============ pass 1: pre1[r-1] = bias1 + Wih1 @ h0[r-1] ============
        {
            ulonglong2 wq[8];
#pragma unroll
            for (int q = 0; q < 8; q++)
                wq[q] = *(const ulonglong2*)__builtin_assume_aligned(w1p + q * 4, 16);
            mv_pass(hp0, wq, prth);
        }
        __syncthreads();
        if (r >= 1 && r < T_STEPS + 1) {
            const int bfull = tid >> 4;
            float s = bias1;
#pragma unroll
            for (int ks = 0; ks < 16; ks++)
                s += part[((ks * 2 + (bfull >> 4)) * 16 + col) * PSTR + (bfull & 15)];
            pre1s[((r - 1) & 1) * 512 + bfull * 16 + col] = s;
        }
        __syncthreads();

        // ============ pass 2: layer-1 gates = pre1[r-2] + Whh1 @ h1[r-3] ============
        {
            ulonglong2 wq[8];
            const float* w2p = w2_s + col * WSTR + ksub * 32;
#pragma unroll
            for (int q = 0; q < 8; q++) wq[q] = *(const ulonglong2*)(w2p + q * 4);
            mv_pass(hp1, wq, prth);
        }
        __syncthreads();
        if (tid < 128 && r >= 2) {
            const int t = r - 2;
            float gs[4];
#pragma unroll
            for (int g = 0; g < 4; g++) {
                int c = g * 4 + ajj;
                float s = pre1s[(r & 1) * 512 + ab * 16 + c];
#pragma unroll
                for (int ks = 0; ks < 16; ks++)
                    s += part[((ks * 2 + bhi) * 16 + c) * PSTR + bl];
                gs[g] = s;
            }
            float i_t = 1.f / (1.f + __expf(-gs[0]));
            float f_t = 1.f / (1.f + __expf(-gs[1]));
            float g_t = __fdividef(2.f, 1.f + __expf(-2.f * gs[2])) - 1.f;
            float o_t = 1.f / (1.f + __expf(-gs[3]));
            float c_new = f_t * c1 + i_t * g_t;
            float tc    = __fdividef(2.f, 1.f + __expf(-2.f * c_new)) - 1.f;
            float h_new = o_t * tc;
            c1 = c_new;
            size_t oidx = ((size_t)(T_STEPS + t) * BATCH + ab) * HID + aj;
            out[oidx]            = h_new;
            out[SECT + oidx]     = c_new;
            out[2 * SECT + oidx] = i_t;
            out[3 * SECT + oidx] = f_t;
            out[4 * SECT + oidx] = g_t;
            out[5 * SECT + oidx] = o_t;
            g_h1[r & 1][ab * HID + aj] = h_new;
        }
        __syncthreads();

        // ---- grid barrier ----
        if (tid == 0) {
            asm volatile("red.release.gpu.global.add.u32 [%0], 1;" :: "l"(&g_bar) : "memory");
            const unsigned target = (unsigned)(r + 1) * NBLK;
            unsigned v;
            do {
                asm volatile("ld.acquire.gpu.global.u32 %0, [%1];" : "=r"(v) : "l"(&g_bar) : "memory");
            } while (v < target);
        }
        __syncthreads();
    }
}

// ---------------- launch ----------------
extern "C" void kernel_launch(void* const* d_in, const int* in_sizes, int n_in,
                              void* d_out, int out_size)
{
    (void)in_sizes; (void)n_in; (void)out_size;
    const float* x    = (const float*)d_in[0];
    const float* w_ih = (const float*)d_in[1];
    const float* w_hh = (const float*)d_in[2];
    const float* b_ih = (const float*)d_in[3];
    const float* b_hh = (const float*)d_in[4];
    float* out = (float*)d_out;

    const int smem = (64 * STRIDE + 512 * PSTR + 16 * WSTR + 2 * 512) * 4;  // 210176 B
    cudaFuncSetAttribute(lstm_fused, cudaFuncAttributeMaxDynamicSharedMemorySize, smem);

    dim3 gg(T_STEPS * BATCH / 128, G4 / 128);  // (128, 16)
    pre_gemm_tc<<<gg, 256>>>(x, w_ih, b_ih, b_hh);   // layer 0 only
    reset_bar<<<1, 1>>>();
    lstm_fused<<<NBLK, 512, smem>>>(w_hh,
                                    w_ih + (size_t)G4 * HID,
                                    w_hh + (size_t)G4 * HID,
                                    b_ih + G4, b_hh + G4, out);
}